// round 2
// baseline (speedup 1.0000x reference)
#include <cuda_runtime.h>
#include <math.h>

#define NTOK 16384
#define DDIM 1024
#define HDIM 4096
#define NEXP 8
#define PROJD 256
#define CAP 12288
#define CLAMP_MAXV 4.605170185988091f  /* log(1/0.01) */

#define BM 128
#define BN 128
#define BK 8
#define TM 8
#define TN 8

// ---------------- device scratch (no cudaMalloc allowed) ----------------
__device__ float g_P[NTOK * PROJD];                       // 16 MB
__device__ float g_simn[PROJD * NEXP];
__device__ int   g_perm[NEXP * CAP];
__device__ int   g_pos[NTOK * 2];
__device__ float g_gate[NTOK * 2];
__device__ int   g_cursor[NEXP];
__device__ float g_H[(size_t)NEXP * CAP * HDIM];          // 1.5 GiB
__device__ float g_F[(size_t)NEXP * CAP * DDIM];          // 384 MiB

// ---------------- small kernels ----------------
__global__ void init_kernel() {
    if (threadIdx.x < NEXP) g_cursor[threadIdx.x] = 0;
}

__global__ void simn_kernel(const float* __restrict__ sim) {
    int e = threadIdx.x;
    if (e < NEXP) {
        float s = 0.f;
        for (int j = 0; j < PROJD; j++) { float v = sim[j * NEXP + e]; s += v * v; }
        float inv = 1.f / fmaxf(sqrtf(s), 1e-12f);
        for (int j = 0; j < PROJD; j++) g_simn[j * NEXP + e] = sim[j * NEXP + e] * inv;
    }
}

// one warp per token: l2norm(P row), logits = projn @ simn * scale, top-2, softmax, route
__global__ void gating_kernel(const float* __restrict__ P,
                              const float* __restrict__ temp) {
    __shared__ float ssim[PROJD * NEXP];
    for (int i = threadIdx.x; i < PROJD * NEXP; i += blockDim.x) ssim[i] = g_simn[i];
    __syncthreads();

    int tok  = (blockIdx.x * blockDim.x + threadIdx.x) >> 5;
    int lane = threadIdx.x & 31;
    if (tok >= NTOK) return;

    const float* row = P + (size_t)tok * PROJD;
    float dot[NEXP];
#pragma unroll
    for (int e = 0; e < NEXP; e++) dot[e] = 0.f;
    float ss = 0.f;
#pragma unroll
    for (int i = 0; i < PROJD / 32; i++) {
        float p = row[lane + 32 * i];
        ss += p * p;
        const float* sr = ssim + (lane + 32 * i) * NEXP;
#pragma unroll
        for (int e = 0; e < NEXP; e++) dot[e] += p * sr[e];
    }
#pragma unroll
    for (int off = 16; off; off >>= 1) {
        ss += __shfl_down_sync(0xffffffffu, ss, off);
#pragma unroll
        for (int e = 0; e < NEXP; e++) dot[e] += __shfl_down_sync(0xffffffffu, dot[e], off);
    }
    if (lane == 0) {
        float scale = expf(fminf(temp[0], CLAMP_MAXV));
        float inv = 1.f / fmaxf(sqrtf(ss), 1e-12f);
        float lg[NEXP];
#pragma unroll
        for (int e = 0; e < NEXP; e++) lg[e] = dot[e] * inv * scale;
        int e0 = 0;
#pragma unroll
        for (int e = 1; e < NEXP; e++) if (lg[e] > lg[e0]) e0 = e;
        int e1 = (e0 == 0) ? 1 : 0;
#pragma unroll
        for (int e = 0; e < NEXP; e++) if (e != e0 && lg[e] > lg[e1]) e1 = e;
        float ex = expf(lg[e1] - lg[e0]);
        float den = 1.f + ex;
        float g0 = 1.f / den;
        float g1 = ex / den;
        int p0 = atomicAdd(&g_cursor[e0], 1); p0 = min(p0, CAP - 1);
        g_perm[e0 * CAP + p0] = tok;
        g_pos[tok * 2 + 0] = e0 * CAP + p0;
        g_gate[tok * 2 + 0] = g0;
        int p1 = atomicAdd(&g_cursor[e1], 1); p1 = min(p1, CAP - 1);
        g_perm[e1 * CAP + p1] = tok;
        g_pos[tok * 2 + 1] = e1 * CAP + p1;
        g_gate[tok * 2 + 1] = g1;
    }
}

// ---------------- generic tiled SGEMM ----------------
// MODE 0: C[M=NTOK,N] = A @ B + bias                        (gating proj)
// MODE 1: H[z-seg]    = gelu(x[perm] @ W1[z] + b1[z])       (expert up-proj)
// MODE 2: F[z-seg]    = H[z-seg] @ W2[z] + b2[z]            (expert down-proj)
template <int MODE>
__global__ __launch_bounds__(256, 2)
void sgemm(const float* __restrict__ A,
           const float* __restrict__ Bw,
           const float* __restrict__ bias,
           float* __restrict__ C,
           const int* __restrict__ perm,
           const int* __restrict__ counts,
           int K, int N) {
    const int z  = blockIdx.z;
    const int mt = blockIdx.y;
    const int nt = blockIdx.x;
    const int M = (MODE == 0) ? NTOK : min(counts[z], CAP);
    if (mt * BM >= M) return;

    __shared__ float As[BK][BM];
    __shared__ float Bs[BK][BN];

    const int tid  = threadIdx.x;
    const int aRow = tid >> 1;
    const int aK   = (tid & 1) * 4;
    const int bK   = tid >> 5;
    const int bN   = (tid & 31) * 4;

    const int rowg = mt * BM + aRow;
    const bool aValid = rowg < M;
    const float* aPtr = A;
    if (aValid) {
        size_t roff;
        if (MODE == 1)      roff = (size_t)perm[(size_t)z * CAP + rowg] * (size_t)K;
        else if (MODE == 2) roff = ((size_t)z * CAP + rowg) * (size_t)K;
        else                roff = (size_t)rowg * (size_t)K;
        aPtr = A + roff + aK;
    }
    const float* bPtr = Bw + (MODE ? (size_t)z * K * N : (size_t)0)
                        + (size_t)bK * N + (size_t)nt * BN + bN;

    const int tr = tid >> 4;   // 0..15
    const int tc = tid & 15;   // 0..15

    float acc[TM][TN];
#pragma unroll
    for (int i = 0; i < TM; i++)
#pragma unroll
        for (int j = 0; j < TN; j++) acc[i][j] = 0.f;

    float4 ra = aValid ? *(const float4*)aPtr : make_float4(0.f, 0.f, 0.f, 0.f);
    float4 rb = *(const float4*)bPtr;

    const int nk = K / BK;
    for (int kt = 0; kt < nk; kt++) {
        As[aK + 0][aRow] = ra.x;
        As[aK + 1][aRow] = ra.y;
        As[aK + 2][aRow] = ra.z;
        As[aK + 3][aRow] = ra.w;
        *(float4*)&Bs[bK][bN] = rb;
        __syncthreads();
        if (kt + 1 < nk) {
            if (aValid) ra = *(const float4*)(aPtr + (size_t)(kt + 1) * BK);
            rb = *(const float4*)(bPtr + (size_t)(kt + 1) * BK * N);
        }
#pragma unroll
        for (int k = 0; k < BK; k++) {
            float4 a0 = *(const float4*)&As[k][tr * TM];
            float4 a1 = *(const float4*)&As[k][tr * TM + 4];
            float4 b0 = *(const float4*)&Bs[k][tc * TN];
            float4 b1 = *(const float4*)&Bs[k][tc * TN + 4];
            float ar[8] = {a0.x, a0.y, a0.z, a0.w, a1.x, a1.y, a1.z, a1.w};
            float br[8] = {b0.x, b0.y, b0.z, b0.w, b1.x, b1.y, b1.z, b1.w};
#pragma unroll
            for (int i = 0; i < TM; i++)
#pragma unroll
                for (int j = 0; j < TN; j++) acc[i][j] += ar[i] * br[j];
        }
        __syncthreads();
    }

    const float* bs = bias + (MODE ? (size_t)z * N : (size_t)0) + nt * BN + tc * TN;
    float bv[TN];
#pragma unroll
    for (int j = 0; j < TN; j++) bv[j] = bs[j];

#pragma unroll
    for (int i = 0; i < TM; i++) {
        int row = mt * BM + tr * TM + i;
        if (row < M) {
            size_t coff;
            if (MODE == 0) coff = (size_t)row * N;
            else           coff = ((size_t)z * CAP + row) * (size_t)N;
            float* cp = C + coff + (size_t)nt * BN + tc * TN;
#pragma unroll
            for (int j = 0; j < TN; j++) {
                float v = acc[i][j] + bv[j];
                if (MODE == 1) v = 0.5f * v * (1.0f + erff(v * 0.70710678118654752f));
                cp[j] = v;
            }
        }
    }
}

// out = x + g0 * F[pos0] + g1 * F[pos1]
__global__ void final_kernel(const float* __restrict__ x, float* __restrict__ out) {
    int idx = blockIdx.x * blockDim.x + threadIdx.x;   // over NTOK*DDIM/4
    int n = idx >> 8;          // DDIM/4 = 256
    int c = idx & 255;
    float4 xv = ((const float4*)x)[idx];
    int p0 = g_pos[n * 2], p1 = g_pos[n * 2 + 1];
    float gg0 = g_gate[n * 2], gg1 = g_gate[n * 2 + 1];
    const float4* F4 = (const float4*)g_F;
    float4 f0 = F4[(size_t)p0 * 256 + c];
    float4 f1 = F4[(size_t)p1 * 256 + c];
    float4 o;
    o.x = xv.x + gg0 * f0.x + gg1 * f1.x;
    o.y = xv.y + gg0 * f0.y + gg1 * f1.y;
    o.z = xv.z + gg0 * f0.z + gg1 * f1.z;
    o.w = xv.w + gg0 * f0.w + gg1 * f1.w;
    ((float4*)out)[idx] = o;
}

// ---------------- launch ----------------
extern "C" void kernel_launch(void* const* d_in, const int* in_sizes, int n_in,
                              void* d_out, int out_size) {
    const float* x    = (const float*)d_in[0];
    const float* Wp   = (const float*)d_in[1];
    const float* bp   = (const float*)d_in[2];
    const float* sim  = (const float*)d_in[3];
    const float* temp = (const float*)d_in[4];
    const float* W1   = (const float*)d_in[5];
    const float* b1   = (const float*)d_in[6];
    const float* W2   = (const float*)d_in[7];
    const float* b2   = (const float*)d_in[8];
    float* out = (float*)d_out;

    void *pP = nullptr, *pH = nullptr, *pF = nullptr, *pPerm = nullptr, *pCur = nullptr;
    cudaGetSymbolAddress(&pP, g_P);
    cudaGetSymbolAddress(&pH, g_H);
    cudaGetSymbolAddress(&pF, g_F);
    cudaGetSymbolAddress(&pPerm, g_perm);
    cudaGetSymbolAddress(&pCur, g_cursor);

    init_kernel<<<1, 32>>>();
    simn_kernel<<<1, 32>>>(sim);

    // P = x @ Wp + bp
    sgemm<0><<<dim3(PROJD / BN, NTOK / BM, 1), 256>>>(
        x, Wp, bp, (float*)pP, nullptr, nullptr, DDIM, PROJD);

    gating_kernel<<<(NTOK * 32) / 256, 256>>>((const float*)pP, temp);

    // H = gelu(x[perm] @ W1[e] + b1[e])
    sgemm<1><<<dim3(HDIM / BN, CAP / BM, NEXP), 256>>>(
        x, W1, b1, (float*)pH, (const int*)pPerm, (const int*)pCur, DDIM, HDIM);

    // F = H @ W2[e] + b2[e]
    sgemm<2><<<dim3(DDIM / BN, CAP / BM, NEXP), 256>>>(
        (const float*)pH, W2, b2, (float*)pF, nullptr, (const int*)pCur, HDIM, DDIM);

    final_kernel<<<(NTOK * DDIM / 4) / 256, 256>>>(x, out);
}